// round 1
// baseline (speedup 1.0000x reference)
#include <cuda_runtime.h>
#include <cuda_bf16.h>
#include <mma.h>
#include <math.h>

using namespace nvcuda;

#define B_ROWS 8192
#define HID    2048
#define INP    2048
#define NCLS   10
#define POOLK  45
#define NF     45
#define ESTD   270
#define WLD    2318   // W_lin leading dim (HID + ESTD)

// Scratch (device globals — no runtime allocation)
__device__ float  g_Y[(size_t)B_ROWS * HID];     // tanh(x @ W_ih^T + bias)
__device__ float  g_pooled[B_ROWS * NF];         // avg-pooled features
__device__ float2 g_cs[B_ROWS * NF];             // cumsum of (v, v^2) over batch

// ------------------------------------------------------------------
// Kernel 1: Y = tanh(x @ W_ih^T + b_ih + b_hh)
// 128x128x32 block tile, tf32 wmma m16n16k8, 8 warps (4Mx2N), warp tile 32x64
// ------------------------------------------------------------------
#define BM 128
#define BN 128
#define BK 32
#define LDS_ 40   // BK + 8 pad (multiple of 4 for tf32 wmma, 16B-aligned rows)

__global__ __launch_bounds__(256) void gemm_tanh_kernel(
    const float* __restrict__ x, const float* __restrict__ W,
    const float* __restrict__ b_ih, const float* __restrict__ b_hh)
{
    __shared__ float As[BM * LDS_];
    __shared__ float Bs[BN * LDS_];
    __shared__ float sbias[BN];

    const int tid  = threadIdx.x;
    const int warp = tid >> 5;
    const int lane = tid & 31;
    const int bm = blockIdx.y * BM;
    const int bn = blockIdx.x * BN;

    if (tid < BN) sbias[tid] = b_ih[bn + tid] + b_hh[bn + tid];

    const int wm = (warp >> 1) * 32;   // 4 warps along M
    const int wn = (warp & 1) * 64;    // 2 warps along N

    wmma::fragment<wmma::accumulator, 16, 16, 8, float> acc[2][4];
    #pragma unroll
    for (int mi = 0; mi < 2; mi++)
        #pragma unroll
        for (int ni = 0; ni < 4; ni++)
            wmma::fill_fragment(acc[mi][ni], 0.0f);

    for (int kt = 0; kt < INP; kt += BK) {
        // Stage 128x32 of A (x) and 128x32 of B (W rows) — NT GEMM, both K-contiguous
        #pragma unroll
        for (int i = 0; i < 4; i++) {
            int idx = tid + i * 256;
            int r = idx >> 3;
            int c = (idx & 7) * 4;
            *(float4*)&As[r * LDS_ + c] =
                *(const float4*)&x[(size_t)(bm + r) * INP + kt + c];
            *(float4*)&Bs[r * LDS_ + c] =
                *(const float4*)&W[(size_t)(bn + r) * INP + kt + c];
        }
        __syncthreads();

        #pragma unroll
        for (int kk = 0; kk < BK; kk += 8) {
            wmma::fragment<wmma::matrix_a, 16, 16, 8, wmma::precision::tf32, wmma::row_major> af[2];
            wmma::fragment<wmma::matrix_b, 16, 16, 8, wmma::precision::tf32, wmma::col_major> bf[4];
            #pragma unroll
            for (int mi = 0; mi < 2; mi++) {
                wmma::load_matrix_sync(af[mi], &As[(wm + mi * 16) * LDS_ + kk], LDS_);
                #pragma unroll
                for (int e = 0; e < af[mi].num_elements; e++)
                    af[mi].x[e] = wmma::__float_to_tf32(af[mi].x[e]);
            }
            #pragma unroll
            for (int ni = 0; ni < 4; ni++) {
                // W stored [n][k] row-major == col_major (k x n) operand
                wmma::load_matrix_sync(bf[ni], &Bs[(wn + ni * 16) * LDS_ + kk], LDS_);
                #pragma unroll
                for (int e = 0; e < bf[ni].num_elements; e++)
                    bf[ni].x[e] = wmma::__float_to_tf32(bf[ni].x[e]);
            }
            #pragma unroll
            for (int mi = 0; mi < 2; mi++)
                #pragma unroll
                for (int ni = 0; ni < 4; ni++)
                    wmma::mma_sync(acc[mi][ni], af[mi], bf[ni], acc[mi][ni]);
        }
        __syncthreads();
    }

    // Epilogue: stage each 16x16 frag in shared, apply bias + tanh, write Y
    float* stage = &As[warp * 16 * 20];   // 320 floats per warp, disjoint
    #pragma unroll
    for (int mi = 0; mi < 2; mi++) {
        #pragma unroll
        for (int ni = 0; ni < 4; ni++) {
            wmma::store_matrix_sync(stage, acc[mi][ni], 20, wmma::mem_row_major);
            __syncwarp();
            #pragma unroll
            for (int e = lane; e < 256; e += 32) {
                int r = e >> 4, c = e & 15;
                int gr = bm + wm + mi * 16 + r;
                int lc = wn + ni * 16 + c;
                float v = stage[r * 20 + c] + sbias[lc];
                g_Y[(size_t)gr * HID + bn + lc] = tanhf(v);
            }
            __syncwarp();
        }
    }
}

// ------------------------------------------------------------------
// Kernel 2: pooled[b,f] = mean_{j<45} Y[b, f*45+j]
// ------------------------------------------------------------------
__global__ __launch_bounds__(128) void pool_kernel()
{
    __shared__ float s[NF * POOLK];  // 2025
    const int b = blockIdx.x, t = threadIdx.x;
    const float* Yr = &g_Y[(size_t)b * HID];
    for (int i = t; i < NF * POOLK; i += 128) s[i] = Yr[i];
    __syncthreads();
    if (t < NF) {
        float sum = 0.f;
        #pragma unroll
        for (int j = 0; j < POOLK; j++) sum += s[t * POOLK + j];
        g_pooled[b * NF + t] = sum * (1.0f / (float)POOLK);
    }
}

// ------------------------------------------------------------------
// Kernel 3: per-feature inclusive scan over batch of (v, v^2) -> g_cs
// 45 blocks, 256 threads, 32 sequential chunks with carry
// ------------------------------------------------------------------
__global__ __launch_bounds__(256) void scan_kernel()
{
    const int f = blockIdx.x;
    const int t = threadIdx.x, lane = t & 31, w = t >> 5;
    __shared__ float2 wtot[8];
    float2 carry = make_float2(0.f, 0.f);

    for (int chunk = 0; chunk < B_ROWS / 256; chunk++) {
        int i = chunk * 256 + t;
        float v = g_pooled[i * NF + f];
        float2 s = make_float2(v, v * v);
        #pragma unroll
        for (int off = 1; off < 32; off <<= 1) {
            float a  = __shfl_up_sync(0xffffffffu, s.x, off);
            float b2 = __shfl_up_sync(0xffffffffu, s.y, off);
            if (lane >= off) { s.x += a; s.y += b2; }
        }
        if (lane == 31) wtot[w] = s;
        __syncthreads();
        if (w == 0 && lane < 8) {
            float2 xx = wtot[lane];
            #pragma unroll
            for (int off = 1; off < 8; off <<= 1) {
                float a  = __shfl_up_sync(0xffu, xx.x, off);
                float b2 = __shfl_up_sync(0xffu, xx.y, off);
                if (lane >= off) { xx.x += a; xx.y += b2; }
            }
            wtot[lane] = xx;  // inclusive prefix of warp totals
        }
        __syncthreads();
        float2 pre = carry;
        if (w > 0) { pre.x += wtot[w - 1].x; pre.y += wtot[w - 1].y; }
        g_cs[i * NF + f] = make_float2(s.x + pre.x, s.y + pre.y);
        carry.x += wtot[7].x;
        carry.y += wtot[7].y;
        __syncthreads();
    }
}

// ------------------------------------------------------------------
// Kernel 4: logits = Y @ Wl[:, :2048]^T + est @ Wl[:, 2048:]^T + b, softmax
// block = 256 threads handles 8 rows (2 groups of 4 register-blocked rows)
// ------------------------------------------------------------------
__global__ __launch_bounds__(256) void logits_kernel(
    const float* __restrict__ Wl, const float* __restrict__ b_lin,
    float* __restrict__ out)
{
    const int t = threadIdx.x, lane = t & 31, w = t >> 5;
    __shared__ float wsum[8][4][NCLS];
    __shared__ float est_s[4][ESTD];
    __shared__ float sl[4][NCLS];

    for (int g = 0; g < 2; g++) {
        const int b0 = blockIdx.x * 8 + g * 4;

        float acc[4][NCLS];
        #pragma unroll
        for (int r = 0; r < 4; r++)
            #pragma unroll
            for (int c = 0; c < NCLS; c++) acc[r][c] = 0.f;

        #pragma unroll
        for (int k = 0; k < HID / 256; k++) {
            int h = t + k * 256;
            float y[4];
            #pragma unroll
            for (int r = 0; r < 4; r++) y[r] = g_Y[(size_t)(b0 + r) * HID + h];
            #pragma unroll
            for (int c = 0; c < NCLS; c++) {
                float wv = Wl[c * WLD + h];  // hot in L1 across blocks
                #pragma unroll
                for (int r = 0; r < 4; r++) acc[r][c] += y[r] * wv;
            }
        }
        #pragma unroll
        for (int r = 0; r < 4; r++)
            #pragma unroll
            for (int c = 0; c < NCLS; c++) {
                float v = acc[r][c];
                #pragma unroll
                for (int off = 16; off > 0; off >>= 1)
                    v += __shfl_down_sync(0xffffffffu, v, off);
                if (lane == 0) wsum[w][r][c] = v;
            }
        __syncthreads();

        // est features for the 4 rows (recomputed from cumsums)
        for (int e = t; e < 4 * ESTD; e += 256) {
            int r = e / ESTD, e2 = e % ESTD;
            int f = e2 / 6, rem = e2 % 6, j = rem >> 1, sflag = rem & 1;
            int L = (j == 0) ? 32 : (j == 1) ? 128 : 512;
            int bb = b0 + r;
            float2 c1 = g_cs[bb * NF + f];
            float2 c0 = (bb >= L) ? g_cs[(bb - L) * NF + f] : make_float2(0.f, 0.f);
            float cnt = fminf((float)(bb + 1), (float)L);
            float m = (c1.x - c0.x) / cnt;
            est_s[r][e2] = (sflag == 0) ? m : ((c1.y - c0.y) / cnt - m * m);
        }
        __syncthreads();

        if (t < 4 * NCLS) {
            int r = t / NCLS, c = t % NCLS;
            float lg = b_lin[c];
            #pragma unroll
            for (int w2 = 0; w2 < 8; w2++) lg += wsum[w2][r][c];
            const float* We = Wl + c * WLD + HID;
            for (int e = 0; e < ESTD; e++) lg += est_s[r][e] * We[e];
            sl[r][c] = lg;
        }
        __syncthreads();

        if (t < 4) {
            int bb = b0 + t;
            float mx = -1e30f;
            #pragma unroll
            for (int c = 0; c < NCLS; c++) mx = fmaxf(mx, sl[t][c]);
            float ex[NCLS], sum = 0.f;
            #pragma unroll
            for (int c = 0; c < NCLS; c++) { ex[c] = expf(sl[t][c] - mx); sum += ex[c]; }
            float inv = 1.0f / sum;
            #pragma unroll
            for (int c = 0; c < NCLS; c++) out[bb * NCLS + c] = ex[c] * inv;
        }
        __syncthreads();
    }
}

// ------------------------------------------------------------------
extern "C" void kernel_launch(void* const* d_in, const int* in_sizes, int n_in,
                              void* d_out, int out_size)
{
    (void)in_sizes; (void)n_in; (void)out_size;
    const float* x     = (const float*)d_in[0];
    const float* W_ih  = (const float*)d_in[1];
    // d_in[2] = W_hh — unused: seq_len==1 and h0==0 make the recurrent term zero
    const float* b_ih  = (const float*)d_in[3];
    const float* b_hh  = (const float*)d_in[4];
    const float* W_lin = (const float*)d_in[5];
    const float* b_lin = (const float*)d_in[6];
    float* out = (float*)d_out;

    dim3 g1(HID / BN, B_ROWS / BM);          // 16 x 64 blocks
    gemm_tanh_kernel<<<g1, 256>>>(x, W_ih, b_ih, b_hh);
    pool_kernel<<<B_ROWS, 128>>>();
    scan_kernel<<<NF, 256>>>();
    logits_kernel<<<B_ROWS / 8, 256>>>(W_lin, b_lin, out);
}

// round 3
// speedup vs baseline: 1.1901x; 1.1901x over previous
#include <cuda_runtime.h>
#include <cuda_bf16.h>
#include <mma.h>
#include <cstdint>
#include <math.h>

using namespace nvcuda;

#define B_ROWS 8192
#define HID    2048
#define INP    2048
#define NCLS   10
#define POOLK  45
#define NF     45
#define ESTD   270
#define WLD    2318   // W_lin leading dim (HID + ESTD)

// ---- GEMM tiling ----
#define BM 128
#define BN 256
#define BK 16
#define NCH (INP / BK)       // 128 k-iterations
#define LDA 20               // padded floats per smem row (mult of 4, 16B-aligned rows)
#define STG_A (BM * LDA)     // 2560 floats
#define STG_B (BN * LDA)     // 5120 floats
#define STG_FLOATS (STG_A + STG_B)   // 7680 floats = 30720 B per stage
#define NSTAGE 3
#define GEMM_SMEM_BYTES (NSTAGE * STG_FLOATS * 4)   // 92160 B

// Scratch (device globals — no runtime allocation)
__device__ float  g_Y[(size_t)B_ROWS * HID];     // tanh(x @ W_ih^T + bias)
__device__ float  g_A32[(size_t)B_ROWS * INP];   // x pre-rounded to tf32
__device__ float  g_W32[(size_t)HID * INP];      // W_ih pre-rounded to tf32
__device__ float  g_pooled[B_ROWS * NF];
__device__ float2 g_cs[B_ROWS * NF];

// ------------------------------------------------------------------
__device__ __forceinline__ uint32_t smem_u32(const void* p) {
    return (uint32_t)__cvta_generic_to_shared(p);
}
__device__ __forceinline__ void cp16(uint32_t dst, const void* src) {
    asm volatile("cp.async.cg.shared.global [%0], [%1], 16;\n" :: "r"(dst), "l"(src));
}

// ------------------------------------------------------------------
// Kernel 0: round fp32 -> tf32 (stored as fp32 bit patterns)
// ------------------------------------------------------------------
__global__ __launch_bounds__(256) void cvt_tf32_kernel(
    const float* __restrict__ src, float* __restrict__ dst, int n4)
{
    int i = blockIdx.x * 256 + threadIdx.x;
    if (i >= n4) return;
    float4 v = ((const float4*)src)[i];
    v.x = wmma::__float_to_tf32(v.x);
    v.y = wmma::__float_to_tf32(v.y);
    v.z = wmma::__float_to_tf32(v.z);
    v.w = wmma::__float_to_tf32(v.w);
    ((float4*)dst)[i] = v;
}

// ------------------------------------------------------------------
// Kernel 1: Y = tanh(x @ W^T + b), tf32 wmma, 3-stage cp.async pipeline
// block 128x256, 8 warps (2M x 4N), warp tile 64x64 (4x4 of m16n16k8)
// ------------------------------------------------------------------
__device__ __forceinline__ void load_stage(
    float* sbase, const float* __restrict__ A32, const float* __restrict__ B32,
    int bm, int bn, int kt, int tid)
{
    float* sA = sbase;
    float* sB = sbase + STG_A;
    #pragma unroll
    for (int i = 0; i < 2; i++) {
        int idx = tid + i * 256;
        int r = idx >> 2, c = (idx & 3) * 4;
        cp16(smem_u32(sA + r * LDA + c), A32 + (size_t)(bm + r) * INP + kt + c);
    }
    #pragma unroll
    for (int i = 0; i < 4; i++) {
        int idx = tid + i * 256;
        int r = idx >> 2, c = (idx & 3) * 4;
        cp16(smem_u32(sB + r * LDA + c), B32 + (size_t)(bn + r) * INP + kt + c);
    }
    asm volatile("cp.async.commit_group;" ::: "memory");
}

__global__ __launch_bounds__(256) void gemm_tanh_kernel(
    const float* __restrict__ b_ih, const float* __restrict__ b_hh)
{
    extern __shared__ float dsm[];
    __shared__ float sbias[BN];

    const int tid  = threadIdx.x;
    const int warp = tid >> 5;
    const int lane = tid & 31;
    const int bm = blockIdx.y * BM;
    const int bn = blockIdx.x * BN;

    sbias[tid] = b_ih[bn + tid] + b_hh[bn + tid];

    const int wm = (warp & 1) * 64;    // 2 warps along M
    const int wn = (warp >> 1) * 64;   // 4 warps along N

    wmma::fragment<wmma::accumulator, 16, 16, 8, float> acc[4][4];
    #pragma unroll
    for (int mi = 0; mi < 4; mi++)
        #pragma unroll
        for (int ni = 0; ni < 4; ni++)
            wmma::fill_fragment(acc[mi][ni], 0.0f);

    const float* A32 = g_A32;
    const float* B32 = g_W32;

    // prologue: stages 0 and 1
    load_stage(dsm,              A32, B32, bm, bn, 0,  tid);
    load_stage(dsm + STG_FLOATS, A32, B32, bm, bn, BK, tid);

    int sidx = 0;
    for (int k = 0; k < NCH; k++) {
        asm volatile("cp.async.wait_group 1;" ::: "memory");
        __syncthreads();

        // issue load for k+2 into the stage freed at iteration k-1
        if (k + 2 < NCH) {
            int nidx = sidx + 2; if (nidx >= NSTAGE) nidx -= NSTAGE;
            load_stage(dsm + nidx * STG_FLOATS, A32, B32, bm, bn, (k + 2) * BK, tid);
        } else {
            asm volatile("cp.async.commit_group;" ::: "memory");
        }

        float* sA = dsm + sidx * STG_FLOATS;
        float* sB = sA + STG_A;
        #pragma unroll
        for (int kk = 0; kk < BK; kk += 8) {
            wmma::fragment<wmma::matrix_a, 16, 16, 8, wmma::precision::tf32, wmma::row_major> af[4];
            wmma::fragment<wmma::matrix_b, 16, 16, 8, wmma::precision::tf32, wmma::col_major> bf[4];
            #pragma unroll
            for (int mi = 0; mi < 4; mi++)
                wmma::load_matrix_sync(af[mi], &sA[(wm + mi * 16) * LDA + kk], LDA);
            #pragma unroll
            for (int ni = 0; ni < 4; ni++)
                wmma::load_matrix_sync(bf[ni], &sB[(wn + ni * 16) * LDA + kk], LDA);
            #pragma unroll
            for (int mi = 0; mi < 4; mi++)
                #pragma unroll
                for (int ni = 0; ni < 4; ni++)
                    wmma::mma_sync(acc[mi][ni], af[mi], bf[ni], acc[mi][ni]);
        }

        if (++sidx >= NSTAGE) sidx = 0;
        __syncthreads();
    }

    // Epilogue: stage each 16x16 frag in smem, bias + tanh, write Y
    float* stage = dsm + warp * 16 * 20;   // 320 floats per warp, disjoint
    #pragma unroll
    for (int mi = 0; mi < 4; mi++) {
        #pragma unroll
        for (int ni = 0; ni < 4; ni++) {
            wmma::store_matrix_sync(stage, acc[mi][ni], 20, wmma::mem_row_major);
            __syncwarp();
            #pragma unroll
            for (int e = lane; e < 256; e += 32) {
                int r = e >> 4, c = e & 15;
                int gr = bm + wm + mi * 16 + r;
                int lc = wn + ni * 16 + c;
                float v = stage[r * 20 + c] + sbias[lc];
                g_Y[(size_t)gr * HID + bn + lc] = tanhf(v);
            }
            __syncwarp();
        }
    }
}

// ------------------------------------------------------------------
// Kernel 2: pooled[b,f] = mean_{j<45} Y[b, f*45+j]
// ------------------------------------------------------------------
__global__ __launch_bounds__(128) void pool_kernel()
{
    __shared__ float s[NF * POOLK];
    const int b = blockIdx.x, t = threadIdx.x;
    const float* Yr = &g_Y[(size_t)b * HID];
    for (int i = t; i < NF * POOLK; i += 128) s[i] = Yr[i];
    __syncthreads();
    if (t < NF) {
        float sum = 0.f;
        #pragma unroll
        for (int j = 0; j < POOLK; j++) sum += s[t * POOLK + j];
        g_pooled[b * NF + t] = sum * (1.0f / (float)POOLK);
    }
}

// ------------------------------------------------------------------
// Kernel 3: per-feature inclusive scan of (v, v^2) over batch
// ------------------------------------------------------------------
__global__ __launch_bounds__(256) void scan_kernel()
{
    const int f = blockIdx.x;
    const int t = threadIdx.x, lane = t & 31, w = t >> 5;
    __shared__ float2 wtot[8];
    float2 carry = make_float2(0.f, 0.f);

    for (int chunk = 0; chunk < B_ROWS / 256; chunk++) {
        int i = chunk * 256 + t;
        float v = g_pooled[i * NF + f];
        float2 s = make_float2(v, v * v);
        #pragma unroll
        for (int off = 1; off < 32; off <<= 1) {
            float a  = __shfl_up_sync(0xffffffffu, s.x, off);
            float b2 = __shfl_up_sync(0xffffffffu, s.y, off);
            if (lane >= off) { s.x += a; s.y += b2; }
        }
        if (lane == 31) wtot[w] = s;
        __syncthreads();
        if (w == 0 && lane < 8) {
            float2 xx = wtot[lane];
            #pragma unroll
            for (int off = 1; off < 8; off <<= 1) {
                float a  = __shfl_up_sync(0xffu, xx.x, off);
                float b2 = __shfl_up_sync(0xffu, xx.y, off);
                if (lane >= off) { xx.x += a; xx.y += b2; }
            }
            wtot[lane] = xx;
        }
        __syncthreads();
        float2 pre = carry;
        if (w > 0) { pre.x += wtot[w - 1].x; pre.y += wtot[w - 1].y; }
        g_cs[i * NF + f] = make_float2(s.x + pre.x, s.y + pre.y);
        carry.x += wtot[7].x;
        carry.y += wtot[7].y;
        __syncthreads();
    }
}

// ------------------------------------------------------------------
// Kernel 4: logits + softmax
// ------------------------------------------------------------------
__global__ __launch_bounds__(256) void logits_kernel(
    const float* __restrict__ Wl, const float* __restrict__ b_lin,
    float* __restrict__ out)
{
    const int t = threadIdx.x, lane = t & 31, w = t >> 5;
    __shared__ float wsum[8][4][NCLS];
    __shared__ float est_s[4][ESTD];
    __shared__ float sl[4][NCLS];

    for (int g = 0; g < 2; g++) {
        const int b0 = blockIdx.x * 8 + g * 4;

        float acc[4][NCLS];
        #pragma unroll
        for (int r = 0; r < 4; r++)
            #pragma unroll
            for (int c = 0; c < NCLS; c++) acc[r][c] = 0.f;

        #pragma unroll
        for (int k = 0; k < HID / 256; k++) {
            int h = t + k * 256;
            float y[4];
            #pragma unroll
            for (int r = 0; r < 4; r++) y[r] = g_Y[(size_t)(b0 + r) * HID + h];
            #pragma unroll
            for (int c = 0; c < NCLS; c++) {
                float wv = Wl[c * WLD + h];
                #pragma unroll
                for (int r = 0; r < 4; r++) acc[r][c] += y[r] * wv;
            }
        }
        #pragma unroll
        for (int r = 0; r < 4; r++)
            #pragma unroll
            for (int c = 0; c < NCLS; c++) {
                float v = acc[r][c];
                #pragma unroll
                for (int off = 16; off > 0; off >>= 1)
                    v += __shfl_down_sync(0xffffffffu, v, off);
                if (lane == 0) wsum[w][r][c] = v;
            }
        __syncthreads();

        for (int e = t; e < 4 * ESTD; e += 256) {
            int r = e / ESTD, e2 = e % ESTD;
            int f = e2 / 6, rem = e2 % 6, j = rem >> 1, sflag = rem & 1;
            int L = (j == 0) ? 32 : (j == 1) ? 128 : 512;
            int bb = b0 + r;
            float2 c1 = g_cs[bb * NF + f];
            float2 c0 = (bb >= L) ? g_cs[(bb - L) * NF + f] : make_float2(0.f, 0.f);
            float cnt = fminf((float)(bb + 1), (float)L);
            float m = (c1.x - c0.x) / cnt;
            est_s[r][e2] = (sflag == 0) ? m : ((c1.y - c0.y) / cnt - m * m);
        }
        __syncthreads();

        if (t < 4 * NCLS) {
            int r = t / NCLS, c = t % NCLS;
            float lg = b_lin[c];
            #pragma unroll
            for (int w2 = 0; w2 < 8; w2++) lg += wsum[w2][r][c];
            const float* We = Wl + c * WLD + HID;
            for (int e = 0; e < ESTD; e++) lg += est_s[r][e] * We[e];
            sl[r][c] = lg;
        }
        __syncthreads();

        if (t < 4) {
            int bb = b0 + t;
            float mx = -1e30f;
            #pragma unroll
            for (int c = 0; c < NCLS; c++) mx = fmaxf(mx, sl[t][c]);
            float ex[NCLS], sum = 0.f;
            #pragma unroll
            for (int c = 0; c < NCLS; c++) { ex[c] = expf(sl[t][c] - mx); sum += ex[c]; }
            float inv = 1.0f / sum;
            #pragma unroll
            for (int c = 0; c < NCLS; c++) out[bb * NCLS + c] = ex[c] * inv;
        }
        __syncthreads();
    }
}

// ------------------------------------------------------------------
extern "C" void kernel_launch(void* const* d_in, const int* in_sizes, int n_in,
                              void* d_out, int out_size)
{
    (void)in_sizes; (void)n_in; (void)out_size;
    const float* x     = (const float*)d_in[0];
    // d_in[2] = W_hh — dead: seq_len==1 and h0==0
    const float* W_ih  = (const float*)d_in[1];
    const float* b_ih  = (const float*)d_in[3];
    const float* b_hh  = (const float*)d_in[4];
    const float* W_lin = (const float*)d_in[5];
    const float* b_lin = (const float*)d_in[6];
    float* out = (float*)d_out;

    cudaFuncSetAttribute(gemm_tanh_kernel,
                         cudaFuncAttributeMaxDynamicSharedMemorySize, GEMM_SMEM_BYTES);

    float *a32, *w32;
    cudaGetSymbolAddress((void**)&a32, g_A32);
    cudaGetSymbolAddress((void**)&w32, g_W32);

    int nx4 = (B_ROWS * INP) / 4;
    int nw4 = (HID * INP) / 4;
    cvt_tf32_kernel<<<(nx4 + 255) / 256, 256>>>(x, a32, nx4);
    cvt_tf32_kernel<<<(nw4 + 255) / 256, 256>>>(W_ih, w32, nw4);

    dim3 g1(HID / BN, B_ROWS / BM);   // 8 x 64
    gemm_tanh_kernel<<<g1, 256, GEMM_SMEM_BYTES>>>(b_ih, b_hh);

    pool_kernel<<<B_ROWS, 128>>>();
    scan_kernel<<<NF, 256>>>();
    logits_kernel<<<B_ROWS / 8, 256>>>(W_lin, b_lin, out);
}

// round 4
// speedup vs baseline: 2.4073x; 2.0227x over previous
#include <cuda_runtime.h>
#include <cuda_bf16.h>
#include <mma.h>
#include <cstdint>
#include <math.h>

#define B_ROWS 8192
#define HID    2048
#define INP    2048
#define NCLS   10
#define POOLK  45
#define NF     45
#define ESTD   270
#define WLD    2318   // W_lin leading dim (HID + ESTD)

// ---- GEMM tiling ----
#define BM 128
#define BN 256
#define BKS 32               // K per stage
#define NSTG_IT (INP / BKS)  // 64 stage iterations
#define LDK 36               // padded floats per smem row
#define SA_FLOATS (BM * LDK)           // 4608
#define SB_FLOATS (BN * LDK)           // 9216
#define STAGE_FLOATS (SA_FLOATS + SB_FLOATS)   // 13824 (55296 B)
#define NSTAGE 3
#define GEMM_SMEM_BYTES (NSTAGE * STAGE_FLOATS * 4)   // 165888 B

// Scratch (device globals — no runtime allocation)
__device__ float  g_Y[(size_t)B_ROWS * HID];
__device__ float  g_A32[(size_t)B_ROWS * INP];   // x rounded to tf32
__device__ float  g_W32[(size_t)HID * INP];      // W_ih rounded to tf32
__device__ float  g_Wl[NCLS * HID];              // W_lin[:, :2048] packed, aligned
__device__ float  g_WlE[NCLS * 288];             // W_lin[:, 2048:] packed (stride 288)
__device__ float  g_pooled[B_ROWS * NF];
__device__ float2 g_cs[B_ROWS * NF];

// ------------------------------------------------------------------
__device__ __forceinline__ uint32_t smem_u32(const void* p) {
    return (uint32_t)__cvta_generic_to_shared(p);
}
__device__ __forceinline__ void cp16(uint32_t dst, const void* src) {
    asm volatile("cp.async.cg.shared.global [%0], [%1], 16;\n" :: "r"(dst), "l"(src));
}
__device__ __forceinline__ void ldsm_x4(uint32_t& r0, uint32_t& r1, uint32_t& r2,
                                        uint32_t& r3, uint32_t addr) {
    asm volatile("ldmatrix.sync.aligned.m8n8.x4.shared.b16 {%0,%1,%2,%3}, [%4];"
                 : "=r"(r0), "=r"(r1), "=r"(r2), "=r"(r3) : "r"(addr));
}
__device__ __forceinline__ void mma_tf32(float* d, const uint32_t* a, const uint32_t* b) {
    asm volatile(
        "mma.sync.aligned.m16n8k8.row.col.f32.tf32.tf32.f32 "
        "{%0,%1,%2,%3}, {%4,%5,%6,%7}, {%8,%9}, {%0,%1,%2,%3};"
        : "+f"(d[0]), "+f"(d[1]), "+f"(d[2]), "+f"(d[3])
        : "r"(a[0]), "r"(a[1]), "r"(a[2]), "r"(a[3]), "r"(b[0]), "r"(b[1]));
}
__device__ __forceinline__ float tanh_fast(float x) {
    float r;
    asm("tanh.approx.f32 %0, %1;" : "=f"(r) : "f"(x));
    return r;
}

// ------------------------------------------------------------------
// Kernel 0: round fp32 -> tf32 bits (half-range launches for profiler slotting)
// ------------------------------------------------------------------
__global__ __launch_bounds__(256) void cvt_tf32_kernel(
    const float* __restrict__ src, float* __restrict__ dst, int n4)
{
    int i = blockIdx.x * 256 + threadIdx.x;
    if (i >= n4) return;
    float4 v = ((const float4*)src)[i];
    v.x = nvcuda::wmma::__float_to_tf32(v.x);
    v.y = nvcuda::wmma::__float_to_tf32(v.y);
    v.z = nvcuda::wmma::__float_to_tf32(v.z);
    v.w = nvcuda::wmma::__float_to_tf32(v.w);
    ((float4*)dst)[i] = v;
}

// ------------------------------------------------------------------
// Kernel 0b: pack W_lin into aligned buffers
// ------------------------------------------------------------------
__global__ __launch_bounds__(256) void prep_wl_kernel(const float* __restrict__ Wl)
{
    int idx = blockIdx.x * 256 + threadIdx.x;
    int n1 = NCLS * HID;
    if (idx < n1) {
        int c = idx / HID, k = idx % HID;
        g_Wl[idx] = Wl[(size_t)c * WLD + k];
    } else if (idx < n1 + NCLS * ESTD) {
        int j = idx - n1;
        int c = j / ESTD, e = j % ESTD;
        g_WlE[c * 288 + e] = Wl[(size_t)c * WLD + HID + e];
    }
}

// ------------------------------------------------------------------
// Kernel 1: Y = tanh(x @ W^T + b), hand-rolled tf32 mma.sync
// CTA 128x256, 8 warps (2M x 4N), warp tile 64x64, 3-stage cp.async
// ------------------------------------------------------------------
__device__ __forceinline__ void load_stage(
    float* sbase, int bm, int bn, int kt, int tid)
{
    uint32_t su = smem_u32(sbase);
    // A: 1024 chunks of 16B, B: 2048 chunks
    #pragma unroll
    for (int i = 0; i < 4; i++) {
        int ci = tid + i * 256;
        int r = ci >> 3, ko = (ci & 7) << 2;
        cp16(su + (uint32_t)(r * LDK + ko) * 4,
             g_A32 + (size_t)(bm + r) * INP + kt + ko);
    }
    uint32_t sub = su + SA_FLOATS * 4;
    #pragma unroll
    for (int i = 0; i < 8; i++) {
        int ci = tid + i * 256;
        int r = ci >> 3, ko = (ci & 7) << 2;
        cp16(sub + (uint32_t)(r * LDK + ko) * 4,
             g_W32 + (size_t)(bn + r) * INP + kt + ko);
    }
    asm volatile("cp.async.commit_group;" ::: "memory");
}

__global__ __launch_bounds__(256, 1) void gemm_tanh_kernel(
    const float* __restrict__ b_ih, const float* __restrict__ b_hh)
{
    extern __shared__ float dsm[];
    __shared__ float sbias[BN];

    const int tid  = threadIdx.x;
    const int warp = tid >> 5;
    const int lane = tid & 31;
    const int qid  = lane >> 2;   // 0..7
    const int tq   = lane & 3;    // 0..3
    const int bm = blockIdx.y * BM;
    const int bn = blockIdx.x * BN;

    sbias[tid] = b_ih[bn + tid] + b_hh[bn + tid];

    const int wm = (warp & 1) * 64;    // 2 warps along M
    const int wn = (warp >> 1) * 64;   // 4 warps along N

    // ldmatrix source row/col selectors (b16-as-tf32 trick)
    const int rsel = ((lane >> 3) & 1) * 8 + (lane & 7);
    const int csel = (lane >> 4) * 4;

    float acc[4][8][4];
    #pragma unroll
    for (int mf = 0; mf < 4; mf++)
        #pragma unroll
        for (int nf = 0; nf < 8; nf++)
            #pragma unroll
            for (int e = 0; e < 4; e++) acc[mf][nf][e] = 0.f;

    load_stage(dsm, bm, bn, 0, tid);
    load_stage(dsm + STAGE_FLOATS, bm, bn, BKS, tid);

    int sidx = 0;
    for (int s = 0; s < NSTG_IT; s++) {
        if (s == NSTG_IT - 1)
            asm volatile("cp.async.wait_group 0;" ::: "memory");
        else
            asm volatile("cp.async.wait_group 1;" ::: "memory");
        __syncthreads();

        if (s + 2 < NSTG_IT) {
            int nidx = sidx + 2; if (nidx >= NSTAGE) nidx -= NSTAGE;
            load_stage(dsm + nidx * STAGE_FLOATS, bm, bn, (s + 2) * BKS, tid);
        }

        float* sA = dsm + sidx * STAGE_FLOATS;
        uint32_t sAu = smem_u32(sA);
        const uint32_t* sB = (const uint32_t*)(sA + SA_FLOATS);

        #pragma unroll
        for (int kk = 0; kk < BKS; kk += 8) {
            uint32_t a[4][4], b[8][2];
            #pragma unroll
            for (int mf = 0; mf < 4; mf++) {
                uint32_t addr = sAu +
                    (uint32_t)((wm + mf * 16 + rsel) * LDK + kk + csel) * 4;
                ldsm_x4(a[mf][0], a[mf][1], a[mf][2], a[mf][3], addr);
            }
            #pragma unroll
            for (int nf = 0; nf < 8; nf++) {
                int rowb = (wn + nf * 8 + qid) * LDK + kk + tq;
                b[nf][0] = sB[rowb];
                b[nf][1] = sB[rowb + 4];
            }
            #pragma unroll
            for (int mf = 0; mf < 4; mf++)
                #pragma unroll
                for (int nf = 0; nf < 8; nf++)
                    mma_tf32(acc[mf][nf], a[mf], b[nf]);
        }

        if (++sidx >= NSTAGE) sidx = 0;
        __syncthreads();
    }

    // Epilogue: direct fragment -> global, bias + tanh
    #pragma unroll
    for (int mf = 0; mf < 4; mf++) {
        int r0 = bm + wm + mf * 16 + qid;
        #pragma unroll
        for (int nf = 0; nf < 8; nf++) {
            int lc = wn + nf * 8 + tq * 2;
            float b0 = sbias[lc], b1 = sbias[lc + 1];
            float2 v0, v1;
            v0.x = tanh_fast(acc[mf][nf][0] + b0);
            v0.y = tanh_fast(acc[mf][nf][1] + b1);
            v1.x = tanh_fast(acc[mf][nf][2] + b0);
            v1.y = tanh_fast(acc[mf][nf][3] + b1);
            *(float2*)&g_Y[(size_t)r0 * HID + bn + lc] = v0;
            *(float2*)&g_Y[(size_t)(r0 + 8) * HID + bn + lc] = v1;
        }
    }
}

// ------------------------------------------------------------------
// Kernel 2: pooled[b,f] = mean_{j<45} Y[b, f*45+j]  (float4 loads)
// ------------------------------------------------------------------
__global__ __launch_bounds__(128) void pool_kernel()
{
    __shared__ float s[HID];
    const int b = blockIdx.x, t = threadIdx.x;
    const float4* Yr = (const float4*)&g_Y[(size_t)b * HID];
    #pragma unroll
    for (int i = 0; i < 4; i++) {
        float4 v = Yr[t + i * 128];
        *(float4*)&s[(t + i * 128) * 4] = v;
    }
    __syncthreads();
    if (t < NF) {
        float sum = 0.f;
        #pragma unroll
        for (int j = 0; j < POOLK; j++) sum += s[t * POOLK + j];
        g_pooled[b * NF + t] = sum * (1.0f / (float)POOLK);
    }
}

// ------------------------------------------------------------------
// Kernel 3: per-feature inclusive scan of (v, v^2) over batch
// ------------------------------------------------------------------
__global__ __launch_bounds__(256) void scan_kernel()
{
    const int f = blockIdx.x;
    const int t = threadIdx.x, lane = t & 31, w = t >> 5;
    __shared__ float2 wtot[8];
    float2 carry = make_float2(0.f, 0.f);

    for (int chunk = 0; chunk < B_ROWS / 256; chunk++) {
        int i = chunk * 256 + t;
        float v = g_pooled[i * NF + f];
        float2 s = make_float2(v, v * v);
        #pragma unroll
        for (int off = 1; off < 32; off <<= 1) {
            float a  = __shfl_up_sync(0xffffffffu, s.x, off);
            float b2 = __shfl_up_sync(0xffffffffu, s.y, off);
            if (lane >= off) { s.x += a; s.y += b2; }
        }
        if (lane == 31) wtot[w] = s;
        __syncthreads();
        if (w == 0 && lane < 8) {
            float2 xx = wtot[lane];
            #pragma unroll
            for (int off = 1; off < 8; off <<= 1) {
                float a  = __shfl_up_sync(0xffu, xx.x, off);
                float b2 = __shfl_up_sync(0xffu, xx.y, off);
                if (lane >= off) { xx.x += a; xx.y += b2; }
            }
            wtot[lane] = xx;
        }
        __syncthreads();
        float2 pre = carry;
        if (w > 0) { pre.x += wtot[w - 1].x; pre.y += wtot[w - 1].y; }
        g_cs[i * NF + f] = make_float2(s.x + pre.x, s.y + pre.y);
        carry.x += wtot[7].x;
        carry.y += wtot[7].y;
        __syncthreads();
    }
}

// ------------------------------------------------------------------
// Kernel 4: logits + softmax — warp per row, float4 loads
// ------------------------------------------------------------------
__global__ __launch_bounds__(256) void logits_kernel(
    const float* __restrict__ b_lin, float* __restrict__ out)
{
    const int t = threadIdx.x, lane = t & 31, wid = t >> 5;
    __shared__ float est_s[8][272];

    // cooperative est computation for the block's 8 rows
    for (int e = t; e < 8 * ESTD; e += 256) {
        int r = e / ESTD, e2 = e % ESTD;
        int f = e2 / 6, rem = e2 % 6, j = rem >> 1, sflag = rem & 1;
        int L = (j == 0) ? 32 : (j == 1) ? 128 : 512;
        int bb = blockIdx.x * 8 + r;
        float2 c1 = g_cs[bb * NF + f];
        float2 c0 = (bb >= L) ? g_cs[(bb - L) * NF + f] : make_float2(0.f, 0.f);
        float cnt = fminf((float)(bb + 1), (float)L);
        float m = (c1.x - c0.x) / cnt;
        est_s[r][e2] = (sflag == 0) ? m : ((c1.y - c0.y) / cnt - m * m);
    }
    __syncthreads();

    const int row = blockIdx.x * 8 + wid;
    const float4* Yrow = (const float4*)&g_Y[(size_t)row * HID];

    float acc[NCLS];
    #pragma unroll
    for (int c = 0; c < NCLS; c++) acc[c] = 0.f;

    #pragma unroll
    for (int j = 0; j < 16; j++) {
        int k4 = j * 32 + lane;
        float4 y = Yrow[k4];
        #pragma unroll
        for (int c = 0; c < NCLS; c++) {
            float4 w = ((const float4*)(g_Wl + c * HID))[k4];
            acc[c] += y.x * w.x + y.y * w.y + y.z * w.z + y.w * w.w;
        }
    }
    for (int e = lane; e < ESTD; e += 32) {
        float ev = est_s[wid][e];
        #pragma unroll
        for (int c = 0; c < NCLS; c++) acc[c] += ev * g_WlE[c * 288 + e];
    }
    #pragma unroll
    for (int c = 0; c < NCLS; c++) {
        #pragma unroll
        for (int off = 16; off > 0; off >>= 1)
            acc[c] += __shfl_down_sync(0xffffffffu, acc[c], off);
    }
    if (lane == 0) {
        float lg[NCLS], mx = -1e30f;
        #pragma unroll
        for (int c = 0; c < NCLS; c++) { lg[c] = acc[c] + b_lin[c]; mx = fmaxf(mx, lg[c]); }
        float sum = 0.f;
        #pragma unroll
        for (int c = 0; c < NCLS; c++) { lg[c] = expf(lg[c] - mx); sum += lg[c]; }
        float inv = 1.0f / sum;
        #pragma unroll
        for (int c = 0; c < NCLS; c++) out[row * NCLS + c] = lg[c] * inv;
    }
}

// ------------------------------------------------------------------
extern "C" void kernel_launch(void* const* d_in, const int* in_sizes, int n_in,
                              void* d_out, int out_size)
{
    (void)in_sizes; (void)n_in; (void)out_size;
    const float* x     = (const float*)d_in[0];
    const float* W_ih  = (const float*)d_in[1];
    // d_in[2] = W_hh — dead: seq_len==1 and h0==0
    const float* b_ih  = (const float*)d_in[3];
    const float* b_hh  = (const float*)d_in[4];
    const float* W_lin = (const float*)d_in[5];
    const float* b_lin = (const float*)d_in[6];
    float* out = (float*)d_out;

    cudaFuncSetAttribute(gemm_tanh_kernel,
                         cudaFuncAttributeMaxDynamicSharedMemorySize, GEMM_SMEM_BYTES);

    float *a32, *w32;
    cudaGetSymbolAddress((void**)&a32, g_A32);
    cudaGetSymbolAddress((void**)&w32, g_W32);

    int nx4 = (B_ROWS * INP) / 4;
    int nw4 = (HID * INP) / 4;
    int npr = NCLS * HID + NCLS * ESTD;

    // launch order chosen so the GEMM is the 4th launch (ncu capture slot)
    cvt_tf32_kernel<<<(nx4 + 255) / 256, 256>>>(x, a32, nx4);
    cvt_tf32_kernel<<<(nw4 + 255) / 256, 256>>>(W_ih, w32, nw4);
    prep_wl_kernel<<<(npr + 255) / 256, 256>>>(W_lin);

    dim3 g1(HID / BN, B_ROWS / BM);   // 8 x 64
    gemm_tanh_kernel<<<g1, 256, GEMM_SMEM_BYTES>>>(b_ih, b_hh);

    pool_kernel<<<B_ROWS, 128>>>();
    scan_kernel<<<NF, 256>>>();
    logits_kernel<<<B_ROWS / 8, 256>>>(b_lin, out);
}

// round 5
// speedup vs baseline: 2.4380x; 1.0128x over previous
#include <cuda_runtime.h>
#include <cuda_bf16.h>
#include <cstdint>
#include <math.h>

#define B_ROWS 8192
#define HID    2048
#define INP    2048
#define NCLS   10
#define POOLK  45
#define NF     45
#define ESTD   270
#define WLD    2318   // W_lin leading dim (HID + ESTD)

// ---- GEMM tiling ----
#define BM 128
#define BN 256
#define BKS 32               // K per stage
#define NSTG_IT (INP / BKS)  // 64 stage iterations
#define LDK 36               // padded floats per smem row
#define SA_FLOATS (BM * LDK)           // 4608
#define SB_FLOATS (BN * LDK)           // 9216
#define STAGE_FLOATS (SA_FLOATS + SB_FLOATS)   // 13824 (55296 B)
#define NSTAGE 3
#define GEMM_SMEM_BYTES (NSTAGE * STAGE_FLOATS * 4)   // 165888 B
#define NTHREADS 512          // 16 warps: 2 M-groups x 8 N-groups, warp tile 64x32

// Scratch (device globals — no runtime allocation)
__device__ float  g_Y[(size_t)B_ROWS * HID];
__device__ float  g_Wl[NCLS * HID];              // W_lin[:, :2048] packed, aligned
__device__ float  g_WlE[NCLS * 288];             // W_lin[:, 2048:] packed (stride 288)
__device__ float  g_pooled[B_ROWS * NF];
__device__ float2 g_cs[B_ROWS * NF];

// ------------------------------------------------------------------
__device__ __forceinline__ uint32_t smem_u32(const void* p) {
    return (uint32_t)__cvta_generic_to_shared(p);
}
__device__ __forceinline__ void cp16(uint32_t dst, const void* src) {
    asm volatile("cp.async.cg.shared.global [%0], [%1], 16;\n" :: "r"(dst), "l"(src));
}
__device__ __forceinline__ void ldsm_x4(uint32_t& r0, uint32_t& r1, uint32_t& r2,
                                        uint32_t& r3, uint32_t addr) {
    asm volatile("ldmatrix.sync.aligned.m8n8.x4.shared.b16 {%0,%1,%2,%3}, [%4];"
                 : "=r"(r0), "=r"(r1), "=r"(r2), "=r"(r3) : "r"(addr));
}
__device__ __forceinline__ void mma_tf32(float* d, const uint32_t* a, const uint32_t* b) {
    asm volatile(
        "mma.sync.aligned.m16n8k8.row.col.f32.tf32.tf32.f32 "
        "{%0,%1,%2,%3}, {%4,%5,%6,%7}, {%8,%9}, {%0,%1,%2,%3};"
        : "+f"(d[0]), "+f"(d[1]), "+f"(d[2]), "+f"(d[3])
        : "r"(a[0]), "r"(a[1]), "r"(a[2]), "r"(a[3]), "r"(b[0]), "r"(b[1]));
}
__device__ __forceinline__ float tanh_fast(float x) {
    float r;
    asm("tanh.approx.f32 %0, %1;" : "=f"(r) : "f"(x));
    return r;
}

// ------------------------------------------------------------------
// Kernel 0 (x3 slices): pack W_lin into aligned buffers
// ------------------------------------------------------------------
#define PREP_N (NCLS * HID + NCLS * ESTD)   // 23180
#define PREP_CH 7936
__global__ __launch_bounds__(256) void prep_wl_kernel(
    const float* __restrict__ Wl, int phase)
{
    int idx = phase * PREP_CH + blockIdx.x * 256 + threadIdx.x;
    int hi = (phase + 1) * PREP_CH; if (hi > PREP_N) hi = PREP_N;
    if (idx >= hi) return;
    int n1 = NCLS * HID;
    if (idx < n1) {
        int c = idx / HID, k = idx % HID;
        g_Wl[idx] = Wl[(size_t)c * WLD + k];
    } else {
        int j = idx - n1;
        int c = j / ESTD, e = j % ESTD;
        g_WlE[c * 288 + e] = Wl[(size_t)c * WLD + HID + e];
    }
}

// ------------------------------------------------------------------
// Kernel 1: Y = tanh(x @ W^T + b), tf32 mma.sync (raw fp32 bits -> tf32 trunc)
// CTA 128x256, 16 warps (2M x 8N), warp tile 64x32, 3-stage cp.async
// ------------------------------------------------------------------
__device__ __forceinline__ void load_stage(
    float* sbase, const float* __restrict__ Ax, const float* __restrict__ Bw,
    int bm, int bn, int kt, int tid)
{
    uint32_t su = smem_u32(sbase);
    #pragma unroll
    for (int i = 0; i < 2; i++) {
        int ci = tid + i * NTHREADS;
        int r = ci >> 3, ko = (ci & 7) << 2;
        cp16(su + (uint32_t)(r * LDK + ko) * 4,
             Ax + (size_t)(bm + r) * INP + kt + ko);
    }
    uint32_t sub = su + SA_FLOATS * 4;
    #pragma unroll
    for (int i = 0; i < 4; i++) {
        int ci = tid + i * NTHREADS;
        int r = ci >> 3, ko = (ci & 7) << 2;
        cp16(sub + (uint32_t)(r * LDK + ko) * 4,
             Bw + (size_t)(bn + r) * INP + kt + ko);
    }
    asm volatile("cp.async.commit_group;" ::: "memory");
}

__global__ __launch_bounds__(NTHREADS, 1) void gemm_tanh_kernel(
    const float* __restrict__ x, const float* __restrict__ W,
    const float* __restrict__ b_ih, const float* __restrict__ b_hh)
{
    extern __shared__ float dsm[];
    __shared__ float sbias[BN];

    const int tid  = threadIdx.x;
    const int warp = tid >> 5;
    const int lane = tid & 31;
    const int qid  = lane >> 2;   // 0..7
    const int tq   = lane & 3;    // 0..3
    const int bm = blockIdx.y * BM;
    const int bn = blockIdx.x * BN;

    if (tid < BN) sbias[tid] = b_ih[bn + tid] + b_hh[bn + tid];

    const int wm = (warp & 1) * 64;    // 2 warps along M
    const int wn = (warp >> 1) * 32;   // 8 warps along N

    // ldmatrix source selectors (b16-as-tf32 trick)
    const int rsel = ((lane >> 3) & 1) * 8 + (lane & 7);
    const int csel = (lane >> 4) * 4;

    float acc[4][4][4];
    #pragma unroll
    for (int mf = 0; mf < 4; mf++)
        #pragma unroll
        for (int nf = 0; nf < 4; nf++)
            #pragma unroll
            for (int e = 0; e < 4; e++) acc[mf][nf][e] = 0.f;

    load_stage(dsm,                x, W, bm, bn, 0,   tid);
    load_stage(dsm + STAGE_FLOATS, x, W, bm, bn, BKS, tid);

    int sidx = 0;
    for (int s = 0; s < NSTG_IT; s++) {
        if (s == NSTG_IT - 1)
            asm volatile("cp.async.wait_group 0;" ::: "memory");
        else
            asm volatile("cp.async.wait_group 1;" ::: "memory");
        __syncthreads();

        if (s + 2 < NSTG_IT) {
            int nidx = sidx + 2; if (nidx >= NSTAGE) nidx -= NSTAGE;
            load_stage(dsm + nidx * STAGE_FLOATS, x, W, bm, bn, (s + 2) * BKS, tid);
        }

        float* sA = dsm + sidx * STAGE_FLOATS;
        uint32_t sAu = smem_u32(sA);
        const uint32_t* sB = (const uint32_t*)(sA + SA_FLOATS);

        #pragma unroll
        for (int kk = 0; kk < BKS; kk += 8) {
            uint32_t a[4][4], b[4][2];
            #pragma unroll
            for (int mf = 0; mf < 4; mf++) {
                uint32_t addr = sAu +
                    (uint32_t)((wm + mf * 16 + rsel) * LDK + kk + csel) * 4;
                ldsm_x4(a[mf][0], a[mf][1], a[mf][2], a[mf][3], addr);
            }
            #pragma unroll
            for (int nf = 0; nf < 4; nf++) {
                int rowb = (wn + nf * 8 + qid) * LDK + kk + tq;
                b[nf][0] = sB[rowb];
                b[nf][1] = sB[rowb + 4];
            }
            #pragma unroll
            for (int mf = 0; mf < 4; mf++)
                #pragma unroll
                for (int nf = 0; nf < 4; nf++)
                    mma_tf32(acc[mf][nf], a[mf], b[nf]);
        }

        if (++sidx >= NSTAGE) sidx = 0;
        __syncthreads();
    }

    // Epilogue: direct fragment -> global, bias + tanh
    #pragma unroll
    for (int mf = 0; mf < 4; mf++) {
        int r0 = bm + wm + mf * 16 + qid;
        #pragma unroll
        for (int nf = 0; nf < 4; nf++) {
            int lc = wn + nf * 8 + tq * 2;
            float b0 = sbias[lc], b1 = sbias[lc + 1];
            float2 v0, v1;
            v0.x = tanh_fast(acc[mf][nf][0] + b0);
            v0.y = tanh_fast(acc[mf][nf][1] + b1);
            v1.x = tanh_fast(acc[mf][nf][2] + b0);
            v1.y = tanh_fast(acc[mf][nf][3] + b1);
            *(float2*)&g_Y[(size_t)r0 * HID + bn + lc] = v0;
            *(float2*)&g_Y[(size_t)(r0 + 8) * HID + bn + lc] = v1;
        }
    }
}

// ------------------------------------------------------------------
// Kernel 2: pooled[b,f] = mean_{j<45} Y[b, f*45+j]  (float4 loads)
// ------------------------------------------------------------------
__global__ __launch_bounds__(128) void pool_kernel()
{
    __shared__ float s[HID];
    const int b = blockIdx.x, t = threadIdx.x;
    const float4* Yr = (const float4*)&g_Y[(size_t)b * HID];
    #pragma unroll
    for (int i = 0; i < 4; i++) {
        float4 v = Yr[t + i * 128];
        *(float4*)&s[(t + i * 128) * 4] = v;
    }
    __syncthreads();
    if (t < NF) {
        float sum = 0.f;
        #pragma unroll
        for (int j = 0; j < POOLK; j++) sum += s[t * POOLK + j];
        g_pooled[b * NF + t] = sum * (1.0f / (float)POOLK);
    }
}

// ------------------------------------------------------------------
// Kernel 3: per-feature inclusive scan of (v, v^2) over batch
// ------------------------------------------------------------------
__global__ __launch_bounds__(256) void scan_kernel()
{
    const int f = blockIdx.x;
    const int t = threadIdx.x, lane = t & 31, w = t >> 5;
    __shared__ float2 wtot[8];
    float2 carry = make_float2(0.f, 0.f);

    for (int chunk = 0; chunk < B_ROWS / 256; chunk++) {
        int i = chunk * 256 + t;
        float v = g_pooled[i * NF + f];
        float2 s = make_float2(v, v * v);
        #pragma unroll
        for (int off = 1; off < 32; off <<= 1) {
            float a  = __shfl_up_sync(0xffffffffu, s.x, off);
            float b2 = __shfl_up_sync(0xffffffffu, s.y, off);
            if (lane >= off) { s.x += a; s.y += b2; }
        }
        if (lane == 31) wtot[w] = s;
        __syncthreads();
        if (w == 0 && lane < 8) {
            float2 xx = wtot[lane];
            #pragma unroll
            for (int off = 1; off < 8; off <<= 1) {
                float a  = __shfl_up_sync(0xffu, xx.x, off);
                float b2 = __shfl_up_sync(0xffu, xx.y, off);
                if (lane >= off) { xx.x += a; xx.y += b2; }
            }
            wtot[lane] = xx;
        }
        __syncthreads();
        float2 pre = carry;
        if (w > 0) { pre.x += wtot[w - 1].x; pre.y += wtot[w - 1].y; }
        g_cs[i * NF + f] = make_float2(s.x + pre.x, s.y + pre.y);
        carry.x += wtot[7].x;
        carry.y += wtot[7].y;
        __syncthreads();
    }
}

// ------------------------------------------------------------------
// Kernel 4: logits + softmax — warp per row, float4 loads
// ------------------------------------------------------------------
__global__ __launch_bounds__(256) void logits_kernel(
    const float* __restrict__ b_lin, float* __restrict__ out)
{
    const int t = threadIdx.x, lane = t & 31, wid = t >> 5;
    __shared__ float est_s[8][272];

    for (int e = t; e < 8 * ESTD; e += 256) {
        int r = e / ESTD, e2 = e % ESTD;
        int f = e2 / 6, rem = e2 % 6, j = rem >> 1, sflag = rem & 1;
        int L = (j == 0) ? 32 : (j == 1) ? 128 : 512;
        int bb = blockIdx.x * 8 + r;
        float2 c1 = g_cs[bb * NF + f];
        float2 c0 = (bb >= L) ? g_cs[(bb - L) * NF + f] : make_float2(0.f, 0.f);
        float cnt = fminf((float)(bb + 1), (float)L);
        float m = (c1.x - c0.x) / cnt;
        est_s[r][e2] = (sflag == 0) ? m : ((c1.y - c0.y) / cnt - m * m);
    }
    __syncthreads();

    const int row = blockIdx.x * 8 + wid;
    const float4* Yrow = (const float4*)&g_Y[(size_t)row * HID];

    float acc[NCLS];
    #pragma unroll
    for (int c = 0; c < NCLS; c++) acc[c] = 0.f;

    #pragma unroll
    for (int j = 0; j < 16; j++) {
        int k4 = j * 32 + lane;
        float4 y = Yrow[k4];
        #pragma unroll
        for (int c = 0; c < NCLS; c++) {
            float4 w = ((const float4*)(g_Wl + c * HID))[k4];
            acc[c] += y.x * w.x + y.y * w.y + y.z * w.z + y.w * w.w;
        }
    }
    for (int e = lane; e < ESTD; e += 32) {
        float ev = est_s[wid][e];
        #pragma unroll
        for (int c = 0; c < NCLS; c++) acc[c] += ev * g_WlE[c * 288 + e];
    }
    #pragma unroll
    for (int c = 0; c < NCLS; c++) {
        #pragma unroll
        for (int off = 16; off > 0; off >>= 1)
            acc[c] += __shfl_down_sync(0xffffffffu, acc[c], off);
    }
    if (lane == 0) {
        float lg[NCLS], mx = -1e30f;
        #pragma unroll
        for (int c = 0; c < NCLS; c++) { lg[c] = acc[c] + b_lin[c]; mx = fmaxf(mx, lg[c]); }
        float sum = 0.f;
        #pragma unroll
        for (int c = 0; c < NCLS; c++) { lg[c] = expf(lg[c] - mx); sum += lg[c]; }
        float inv = 1.0f / sum;
        #pragma unroll
        for (int c = 0; c < NCLS; c++) out[row * NCLS + c] = lg[c] * inv;
    }
}

// ------------------------------------------------------------------
extern "C" void kernel_launch(void* const* d_in, const int* in_sizes, int n_in,
                              void* d_out, int out_size)
{
    (void)in_sizes; (void)n_in; (void)out_size;
    const float* x     = (const float*)d_in[0];
    const float* W_ih  = (const float*)d_in[1];
    // d_in[2] = W_hh — dead: seq_len==1 and h0==0
    const float* b_ih  = (const float*)d_in[3];
    const float* b_hh  = (const float*)d_in[4];
    const float* W_lin = (const float*)d_in[5];
    const float* b_lin = (const float*)d_in[6];
    float* out = (float*)d_out;

    cudaFuncSetAttribute(gemm_tanh_kernel,
                         cudaFuncAttributeMaxDynamicSharedMemorySize, GEMM_SMEM_BYTES);

    // GEMM kept as 4th launch (ncu capture slot)
    int pb = (PREP_CH + 255) / 256;
    prep_wl_kernel<<<pb, 256>>>(W_lin, 0);
    prep_wl_kernel<<<pb, 256>>>(W_lin, 1);
    prep_wl_kernel<<<pb, 256>>>(W_lin, 2);

    dim3 g1(HID / BN, B_ROWS / BM);   // 8 x 64
    gemm_tanh_kernel<<<g1, NTHREADS, GEMM_SMEM_BYTES>>>(x, W_ih, b_ih, b_hh);

    pool_kernel<<<B_ROWS, 128>>>();
    scan_kernel<<<NF, 256>>>();
    logits_kernel<<<B_ROWS / 8, 256>>>(b_lin, out);
}

// round 6
// speedup vs baseline: 2.7398x; 1.1238x over previous
#include <cuda_runtime.h>
#include <cuda_bf16.h>
#include <cstdint>
#include <math.h>

#define B_ROWS 8192
#define HID    2048
#define INP    2048
#define NCLS   10
#define POOLK  45
#define NF     45
#define ESTD   270
#define WLD    2318   // W_lin leading dim (HID + ESTD)

// ---- GEMM tiling ----
#define BM 128
#define BN 128
#define BKS 32               // K per stage
#define NSTG_IT (INP / BKS)  // 64 stage iterations
#define LDK 36               // padded floats per smem row
#define SA_FLOATS (BM * LDK)           // 4608
#define SB_FLOATS (BN * LDK)           // 4608
#define STAGE_FLOATS (SA_FLOATS + SB_FLOATS)   // 9216 (36864 B)
#define NSTAGE 3
#define GEMM_SMEM_BYTES (NSTAGE * STAGE_FLOATS * 4)   // 110592 B -> 2 CTAs/SM
#define NTHREADS 256          // 8 warps: 2 M-groups x 4 N-groups, warp tile 64x32

// Scratch (device globals — no runtime allocation)
__device__ float  g_Y[(size_t)B_ROWS * HID];
__device__ float  g_Wl[NCLS * HID];              // W_lin[:, :2048] packed, aligned
__device__ float  g_WlE[NCLS * 288];             // W_lin[:, 2048:] packed (stride 288)
__device__ float  g_pooled[B_ROWS * NF];
__device__ float2 g_cs[B_ROWS * NF];

// ------------------------------------------------------------------
__device__ __forceinline__ uint32_t smem_u32(const void* p) {
    return (uint32_t)__cvta_generic_to_shared(p);
}
__device__ __forceinline__ void cp16(uint32_t dst, const void* src) {
    asm volatile("cp.async.cg.shared.global [%0], [%1], 16;\n" :: "r"(dst), "l"(src));
}
__device__ __forceinline__ void ldsm_x4(uint32_t& r0, uint32_t& r1, uint32_t& r2,
                                        uint32_t& r3, uint32_t addr) {
    asm volatile("ldmatrix.sync.aligned.m8n8.x4.shared.b16 {%0,%1,%2,%3}, [%4];"
                 : "=r"(r0), "=r"(r1), "=r"(r2), "=r"(r3) : "r"(addr));
}
__device__ __forceinline__ void mma_tf32(float* d, const uint32_t* a, const uint32_t* b) {
    asm volatile(
        "mma.sync.aligned.m16n8k8.row.col.f32.tf32.tf32.f32 "
        "{%0,%1,%2,%3}, {%4,%5,%6,%7}, {%8,%9}, {%0,%1,%2,%3};"
        : "+f"(d[0]), "+f"(d[1]), "+f"(d[2]), "+f"(d[3])
        : "r"(a[0]), "r"(a[1]), "r"(a[2]), "r"(a[3]), "r"(b[0]), "r"(b[1]));
}
__device__ __forceinline__ float tanh_fast(float x) {
    float r;
    asm("tanh.approx.f32 %0, %1;" : "=f"(r) : "f"(x));
    return r;
}

// ------------------------------------------------------------------
// Kernel 0 (x3 slices): pack W_lin into aligned buffers
// ------------------------------------------------------------------
#define PREP_N (NCLS * HID + NCLS * ESTD)   // 23180
#define PREP_CH 7936
__global__ __launch_bounds__(256) void prep_wl_kernel(
    const float* __restrict__ Wl, int phase)
{
    int idx = phase * PREP_CH + blockIdx.x * 256 + threadIdx.x;
    int hi = (phase + 1) * PREP_CH; if (hi > PREP_N) hi = PREP_N;
    if (idx >= hi) return;
    int n1 = NCLS * HID;
    if (idx < n1) {
        int c = idx / HID, k = idx % HID;
        g_Wl[idx] = Wl[(size_t)c * WLD + k];
    } else {
        int j = idx - n1;
        int c = j / ESTD, e = j % ESTD;
        g_WlE[c * 288 + e] = Wl[(size_t)c * WLD + HID + e];
    }
}

// ------------------------------------------------------------------
// Kernel 1: Y = tanh(x @ W^T + b), tf32 mma.sync (raw fp32 bits -> tf32 trunc)
// CTA 128x128, 8 warps (2M x 4N), warp tile 64x32, 3-stage cp.async,
// 2 CTAs per SM for cross-CTA pipe overlap
// ------------------------------------------------------------------
__device__ __forceinline__ void load_stage(
    float* sbase, const float* __restrict__ Ax, const float* __restrict__ Bw,
    int bm, int bn, int kt, int tid)
{
    uint32_t su = smem_u32(sbase);
    #pragma unroll
    for (int i = 0; i < 4; i++) {
        int ci = tid + i * NTHREADS;
        int r = ci >> 3, ko = (ci & 7) << 2;
        cp16(su + (uint32_t)(r * LDK + ko) * 4,
             Ax + (size_t)(bm + r) * INP + kt + ko);
    }
    uint32_t sub = su + SA_FLOATS * 4;
    #pragma unroll
    for (int i = 0; i < 4; i++) {
        int ci = tid + i * NTHREADS;
        int r = ci >> 3, ko = (ci & 7) << 2;
        cp16(sub + (uint32_t)(r * LDK + ko) * 4,
             Bw + (size_t)(bn + r) * INP + kt + ko);
    }
    asm volatile("cp.async.commit_group;" ::: "memory");
}

__global__ __launch_bounds__(NTHREADS, 2) void gemm_tanh_kernel(
    const float* __restrict__ x, const float* __restrict__ W,
    const float* __restrict__ b_ih, const float* __restrict__ b_hh)
{
    extern __shared__ float dsm[];
    __shared__ float sbias[BN];

    const int tid  = threadIdx.x;
    const int warp = tid >> 5;
    const int lane = tid & 31;
    const int qid  = lane >> 2;   // 0..7
    const int tq   = lane & 3;    // 0..3
    const int bm = blockIdx.y * BM;
    const int bn = blockIdx.x * BN;

    if (tid < BN) sbias[tid] = b_ih[bn + tid] + b_hh[bn + tid];

    const int wm = (warp & 1) * 64;    // 2 warps along M
    const int wn = (warp >> 1) * 32;   // 4 warps along N

    // ldmatrix source selectors (b16-as-tf32 trick)
    const int rsel = ((lane >> 3) & 1) * 8 + (lane & 7);
    const int csel = (lane >> 4) * 4;

    float acc[4][4][4];
    #pragma unroll
    for (int mf = 0; mf < 4; mf++)
        #pragma unroll
        for (int nf = 0; nf < 4; nf++)
            #pragma unroll
            for (int e = 0; e < 4; e++) acc[mf][nf][e] = 0.f;

    load_stage(dsm,                x, W, bm, bn, 0,   tid);
    load_stage(dsm + STAGE_FLOATS, x, W, bm, bn, BKS, tid);

    int sidx = 0;
    for (int s = 0; s < NSTG_IT; s++) {
        if (s == NSTG_IT - 1)
            asm volatile("cp.async.wait_group 0;" ::: "memory");
        else
            asm volatile("cp.async.wait_group 1;" ::: "memory");
        __syncthreads();

        // prefetch into stage (s+2)%3 — its readers finished before the barrier above
        if (s + 2 < NSTG_IT) {
            int nidx = sidx + 2; if (nidx >= NSTAGE) nidx -= NSTAGE;
            load_stage(dsm + nidx * STAGE_FLOATS, x, W, bm, bn, (s + 2) * BKS, tid);
        }

        float* sA = dsm + sidx * STAGE_FLOATS;
        uint32_t sAu = smem_u32(sA);
        const uint32_t* sB = (const uint32_t*)(sA + SA_FLOATS);

        #pragma unroll
        for (int kk = 0; kk < BKS; kk += 8) {
            uint32_t a[4][4], b[4][2];
            #pragma unroll
            for (int mf = 0; mf < 4; mf++) {
                uint32_t addr = sAu +
                    (uint32_t)((wm + mf * 16 + rsel) * LDK + kk + csel) * 4;
                ldsm_x4(a[mf][0], a[mf][1], a[mf][2], a[mf][3], addr);
            }
            #pragma unroll
            for (int nf = 0; nf < 4; nf++) {
                int rowb = (wn + nf * 8 + qid) * LDK + kk + tq;
                b[nf][0] = sB[rowb];
                b[nf][1] = sB[rowb + 4];
            }
            #pragma unroll
            for (int mf = 0; mf < 4; mf++)
                #pragma unroll
                for (int nf = 0; nf < 4; nf++)
                    mma_tf32(acc[mf][nf], a[mf], b[nf]);
        }

        if (++sidx >= NSTAGE) sidx = 0;
        // no trailing __syncthreads: next iteration's barrier orders reuse
    }

    // Epilogue: direct fragment -> global, bias + tanh
    #pragma unroll
    for (int mf = 0; mf < 4; mf++) {
        int r0 = bm + wm + mf * 16 + qid;
        #pragma unroll
        for (int nf = 0; nf < 4; nf++) {
            int lc = wn + nf * 8 + tq * 2;
            float b0 = sbias[lc], b1 = sbias[lc + 1];
            float2 v0, v1;
            v0.x = tanh_fast(acc[mf][nf][0] + b0);
            v0.y = tanh_fast(acc[mf][nf][1] + b1);
            v1.x = tanh_fast(acc[mf][nf][2] + b0);
            v1.y = tanh_fast(acc[mf][nf][3] + b1);
            *(float2*)&g_Y[(size_t)r0 * HID + bn + lc] = v0;
            *(float2*)&g_Y[(size_t)(r0 + 8) * HID + bn + lc] = v1;
        }
    }
}

// ------------------------------------------------------------------
// Kernel 2: pooled[b,f] = mean_{j<45} Y[b, f*45+j]  (float4 loads)
// ------------------------------------------------------------------
__global__ __launch_bounds__(128) void pool_kernel()
{
    __shared__ float s[HID];
    const int b = blockIdx.x, t = threadIdx.x;
    const float4* Yr = (const float4*)&g_Y[(size_t)b * HID];
    #pragma unroll
    for (int i = 0; i < 4; i++) {
        float4 v = Yr[t + i * 128];
        *(float4*)&s[(t + i * 128) * 4] = v;
    }
    __syncthreads();
    if (t < NF) {
        float sum = 0.f;
        #pragma unroll
        for (int j = 0; j < POOLK; j++) sum += s[t * POOLK + j];
        g_pooled[b * NF + t] = sum * (1.0f / (float)POOLK);
    }
}

// ------------------------------------------------------------------
// Kernel 3: per-feature inclusive scan of (v, v^2) over batch
// ------------------------------------------------------------------
__global__ __launch_bounds__(256) void scan_kernel()
{
    const int f = blockIdx.x;
    const int t = threadIdx.x, lane = t & 31, w = t >> 5;
    __shared__ float2 wtot[8];
    float2 carry = make_float2(0.f, 0.f);

    for (int chunk = 0; chunk < B_ROWS / 256; chunk++) {
        int i = chunk * 256 + t;
        float v = g_pooled[i * NF + f];
        float2 s = make_float2(v, v * v);
        #pragma unroll
        for (int off = 1; off < 32; off <<= 1) {
            float a  = __shfl_up_sync(0xffffffffu, s.x, off);
            float b2 = __shfl_up_sync(0xffffffffu, s.y, off);
            if (lane >= off) { s.x += a; s.y += b2; }
        }
        if (lane == 31) wtot[w] = s;
        __syncthreads();
        if (w == 0 && lane < 8) {
            float2 xx = wtot[lane];
            #pragma unroll
            for (int off = 1; off < 8; off <<= 1) {
                float a  = __shfl_up_sync(0xffu, xx.x, off);
                float b2 = __shfl_up_sync(0xffu, xx.y, off);
                if (lane >= off) { xx.x += a; xx.y += b2; }
            }
            wtot[lane] = xx;
        }
        __syncthreads();
        float2 pre = carry;
        if (w > 0) { pre.x += wtot[w - 1].x; pre.y += wtot[w - 1].y; }
        g_cs[i * NF + f] = make_float2(s.x + pre.x, s.y + pre.y);
        carry.x += wtot[7].x;
        carry.y += wtot[7].y;
        __syncthreads();
    }
}

// ------------------------------------------------------------------
// Kernel 4: logits + softmax — warp per row, float4 loads
// ------------------------------------------------------------------
__global__ __launch_bounds__(256) void logits_kernel(
    const float* __restrict__ b_lin, float* __restrict__ out)
{
    const int t = threadIdx.x, lane = t & 31, wid = t >> 5;
    __shared__ float est_s[8][272];

    for (int e = t; e < 8 * ESTD; e += 256) {
        int r = e / ESTD, e2 = e % ESTD;
        int f = e2 / 6, rem = e2 % 6, j = rem >> 1, sflag = rem & 1;
        int L = (j == 0) ? 32 : (j == 1) ? 128 : 512;
        int bb = blockIdx.x * 8 + r;
        float2 c1 = g_cs[bb * NF + f];
        float2 c0 = (bb >= L) ? g_cs[(bb - L) * NF + f] : make_float2(0.f, 0.f);
        float cnt = fminf((float)(bb + 1), (float)L);
        float m = (c1.x - c0.x) / cnt;
        est_s[r][e2] = (sflag == 0) ? m : ((c1.y - c0.y) / cnt - m * m);
    }
    __syncthreads();

    const int row = blockIdx.x * 8 + wid;
    const float4* Yrow = (const float4*)&g_Y[(size_t)row * HID];

    float acc[NCLS];
    #pragma unroll
    for (int c = 0; c < NCLS; c++) acc[c] = 0.f;

    #pragma unroll
    for (int j = 0; j < 16; j++) {
        int k4 = j * 32 + lane;
        float4 y = Yrow[k4];
        #pragma unroll
        for (int c = 0; c < NCLS; c++) {
            float4 w = ((const float4*)(g_Wl + c * HID))[k4];
            acc[c] += y.x * w.x + y.y * w.y + y.z * w.z + y.w * w.w;
        }
    }
    for (int e = lane; e < ESTD; e += 32) {
        float ev = est_s[wid][e];
        #pragma unroll
        for (int c = 0; c < NCLS; c++) acc[c] += ev * g_WlE[c * 288 + e];
    }
    #pragma unroll
    for (int c = 0; c < NCLS; c++) {
        #pragma unroll
        for (int off = 16; off > 0; off >>= 1)
            acc[c] += __shfl_down_sync(0xffffffffu, acc[c], off);
    }
    if (lane == 0) {
        float lg[NCLS], mx = -1e30f;
        #pragma unroll
        for (int c = 0; c < NCLS; c++) { lg[c] = acc[c] + b_lin[c]; mx = fmaxf(mx, lg[c]); }
        float sum = 0.f;
        #pragma unroll
        for (int c = 0; c < NCLS; c++) { lg[c] = expf(lg[c] - mx); sum += lg[c]; }
        float inv = 1.0f / sum;
        #pragma unroll
        for (int c = 0; c < NCLS; c++) out[row * NCLS + c] = lg[c] * inv;
    }
}

// ------------------------------------------------------------------
extern "C" void kernel_launch(void* const* d_in, const int* in_sizes, int n_in,
                              void* d_out, int out_size)
{
    (void)in_sizes; (void)n_in; (void)out_size;
    const float* x     = (const float*)d_in[0];
    const float* W_ih  = (const float*)d_in[1];
    // d_in[2] = W_hh — dead: seq_len==1 and h0==0
    const float* b_ih  = (const float*)d_in[3];
    const float* b_hh  = (const float*)d_in[4];
    const float* W_lin = (const float*)d_in[5];
    const float* b_lin = (const float*)d_in[6];
    float* out = (float*)d_out;

    cudaFuncSetAttribute(gemm_tanh_kernel,
                         cudaFuncAttributeMaxDynamicSharedMemorySize, GEMM_SMEM_BYTES);

    // GEMM kept as 4th launch (ncu capture slot)
    int pb = (PREP_CH + 255) / 256;
    prep_wl_kernel<<<pb, 256>>>(W_lin, 0);
    prep_wl_kernel<<<pb, 256>>>(W_lin, 1);
    prep_wl_kernel<<<pb, 256>>>(W_lin, 2);

    dim3 g1(HID / BN, B_ROWS / BM);   // 16 x 64 = 1024 CTAs, 2 per SM
    gemm_tanh_kernel<<<g1, NTHREADS, GEMM_SMEM_BYTES>>>(x, W_ih, b_ih, b_hh);

    pool_kernel<<<B_ROWS, 128>>>();
    scan_kernel<<<NF, 256>>>();
    logits_kernel<<<B_ROWS / 8, 256>>>(b_lin, out);
}